// round 7
// baseline (speedup 1.0000x reference)
#include <cuda_runtime.h>
#include <cuda_bf16.h>
#include <mma.h>
#include <math.h>
#include <stdint.h>

using namespace nvcuda;

#define NN   30000
#define TT   16
#define DE   32
#define HE   128
#define F3   384
#define NE0  300000
#define NE   330000
#define NT   3000
#define HD   256
#define OUTL 25

// ---------------- scratch (static device arrays; no allocations) ----------------
__device__ __align__(256) float g_EMB[NN*TT*DE];
__device__ __align__(256) float g_GX[(long)NN*TT*F3];   // permuted x-projection, all t
__device__ __align__(256) float g_H[NN*HE];
__device__ __align__(256) float g_HENC[NN*HE];
__device__ __align__(256) float g_F1[NN*F3];
__device__ __align__(256) float g_O1[NN*F3];
__device__ __align__(256) float g_F2[NN*F3];
__device__ __align__(256) float g_O2[NN*F3];
__device__ __align__(256) float g_asv[NN*3];
__device__ __align__(256) float g_adv[NN*3];
__device__ __align__(256) float g_ENC[NT*HE];
__device__ __align__(256) float g_X0[NT*4*HD];          // permuted
__device__ __align__(256) float g_c0[NT*HD];
__device__ __align__(256) float g_c1[NT*HD];
__device__ int g_cnt[NN];
__device__ int g_offs[NN+1];
__device__ int g_cur[NN];
__device__ int g_ssrc[NE];
// permuted biases
__device__ float g_gbxp[F3];
__device__ float g_gbhp[F3];
__device__ float g_l0bp[4*HD];
__device__ float g_l1bp[4*HD];
// transposed bf16 hi/lo weights [N,K] (gate-permuted where noted)
#define WT_TOTAL 1200000
__device__ __align__(256) __nv_bfloat16 g_WThi[WT_TOTAL];
__device__ __align__(256) __nv_bfloat16 g_WTlo[WT_TOTAL];

__device__ __forceinline__ float sigf(float x){ return 1.f/(1.f+__expf(-x)); }
__device__ __forceinline__ float lk01(float x){ return x>=0.f? x : 0.1f*x; }

// ---------------- utility ----------------
__global__ void zero_i(int* __restrict__ p, int n){
    int i = blockIdx.x*blockDim.x + threadIdx.x;
    if (i < n) p[i] = 0;
}

// weight transpose + bf16 hi/lo split + gate permutation:
// W[K,N] fp32 -> hi/lo bf16 at [np*ldk + kofs + k], np = (n % (N/P))*P + n/(N/P)
// ldk/kofs let two K-blocks (e.g. l1Wx | l1Wh) pack into one [N', Kx+Kh] matrix.
__global__ void wsplitp(const float* __restrict__ W, __nv_bfloat16* __restrict__ hi,
                        __nv_bfloat16* __restrict__ lo, int K, int N, int P,
                        int ldk, int kofs)
{
    int idx = blockIdx.x*blockDim.x + threadIdx.x;
    if (idx >= K*N) return;
    int k = idx / N, n = idx - k*N;
    int Gp = N / P;
    int np = (n % Gp)*P + n/Gp;
    float v = W[idx];
    __nv_bfloat16 h = __float2bfloat16(v);
    hi[(long)np*ldk + kofs + k] = h;
    lo[(long)np*ldk + kofs + k] = __float2bfloat16(v - __bfloat162float(h));
}

__global__ void bperm(const float* __restrict__ b, float* __restrict__ bp, int N, int P)
{
    int n = blockIdx.x*blockDim.x + threadIdx.x;
    if (n >= N) return;
    int Gp = N / P;
    bp[(n % Gp)*P + n/Gp] = b[n];
}

// ---------------- WMMA bf16x3 GEMM (feed-forward layers) ----------------
#define WBM 128
#define WBN 64
#define WBK 32
#define SKA 40
#define SKB 40
#define SCC 72
#define MMA_SMEM 36864

typedef wmma::fragment<wmma::matrix_a, 16,16,16, __nv_bfloat16, wmma::row_major> FragA;
typedef wmma::fragment<wmma::matrix_b, 16,16,16, __nv_bfloat16, wmma::col_major> FragB;
typedef wmma::fragment<wmma::accumulator, 16,16,16, float> FragC;

__global__ void __launch_bounds__(256,2)
mma_gemm(const float* __restrict__ A1, const __nv_bfloat16* __restrict__ W1h,
         const __nv_bfloat16* __restrict__ W1l, int K1,
         const float* __restrict__ bias, const float* __restrict__ add,
         float* __restrict__ C, int M, int N)
{
    extern __shared__ char smc[];
    __nv_bfloat16* Ah = (__nv_bfloat16*)smc;
    __nv_bfloat16* Al = Ah + WBM*SKA;
    __nv_bfloat16* Bh = Al + WBM*SKA;
    __nv_bfloat16* Bl = Bh + WBN*SKB;
    float* Cs = (float*)smc;

    const int tid = threadIdx.x, wid = tid >> 5;
    const int warp_m = wid >> 1, warp_n = wid & 1;
    const long bm = (long)blockIdx.y * WBM;
    const int bn = blockIdx.x * WBN;

    FragC acc[2][2];
    #pragma unroll
    for (int mm = 0; mm < 2; ++mm)
        #pragma unroll
        for (int nn = 0; nn < 2; ++nn)
            wmma::fill_fragment(acc[mm][nn], 0.f);

    for (int k0 = 0; k0 < K1; k0 += WBK) {
        #pragma unroll
        for (int i = 0; i < 4; ++i) {
            int li = tid + (i << 8);
            int r = li >> 3, c = (li & 7) << 2;
            float4 v = make_float4(0.f,0.f,0.f,0.f);
            if (bm + r < M) v = *(const float4*)(A1 + (bm+r)*K1 + k0 + c);
            __nv_bfloat16 hx = __float2bfloat16(v.x);
            __nv_bfloat16 hy = __float2bfloat16(v.y);
            __nv_bfloat16 hz = __float2bfloat16(v.z);
            __nv_bfloat16 hw = __float2bfloat16(v.w);
            int o = r*SKA + c;
            Ah[o]   = hx; Ah[o+1] = hy; Ah[o+2] = hz; Ah[o+3] = hw;
            Al[o]   = __float2bfloat16(v.x - __bfloat162float(hx));
            Al[o+1] = __float2bfloat16(v.y - __bfloat162float(hy));
            Al[o+2] = __float2bfloat16(v.z - __bfloat162float(hz));
            Al[o+3] = __float2bfloat16(v.w - __bfloat162float(hw));
        }
        {
            int r = tid >> 2, c = (tid & 3) << 3;
            long go = (long)(bn + r)*K1 + k0 + c;
            *(uint4*)&Bh[r*SKB + c] = *(const uint4*)(W1h + go);
            *(uint4*)&Bl[r*SKB + c] = *(const uint4*)(W1l + go);
        }
        __syncthreads();

        #pragma unroll
        for (int kk = 0; kk < WBK; kk += 16) {
            FragA ah[2], al[2];
            FragB bh[2], bl[2];
            #pragma unroll
            for (int mm = 0; mm < 2; ++mm) {
                int ro = (warp_m*32 + mm*16)*SKA + kk;
                wmma::load_matrix_sync(ah[mm], Ah + ro, SKA);
                wmma::load_matrix_sync(al[mm], Al + ro, SKA);
            }
            #pragma unroll
            for (int nn = 0; nn < 2; ++nn) {
                int no = (warp_n*32 + nn*16)*SKB + kk;
                wmma::load_matrix_sync(bh[nn], Bh + no, SKB);
                wmma::load_matrix_sync(bl[nn], Bl + no, SKB);
            }
            #pragma unroll
            for (int mm = 0; mm < 2; ++mm)
                #pragma unroll
                for (int nn = 0; nn < 2; ++nn) {
                    wmma::mma_sync(acc[mm][nn], ah[mm], bh[nn], acc[mm][nn]);
                    wmma::mma_sync(acc[mm][nn], ah[mm], bl[nn], acc[mm][nn]);
                    wmma::mma_sync(acc[mm][nn], al[mm], bh[nn], acc[mm][nn]);
                }
        }
        __syncthreads();
    }

    #pragma unroll
    for (int mm = 0; mm < 2; ++mm)
        #pragma unroll
        for (int nn = 0; nn < 2; ++nn)
            wmma::store_matrix_sync(Cs + (warp_m*32 + mm*16)*SCC + warp_n*32 + nn*16,
                                    acc[mm][nn], SCC, wmma::mem_row_major);
    __syncthreads();

    #pragma unroll
    for (int i = 0; i < 8; ++i) {
        int li = tid + (i << 8);
        int r = li >> 4, c = (li & 15) << 2;
        long row = bm + r;
        if (row >= M) continue;
        float4 v = *(float4*)&Cs[r*SCC + c];
        int col = bn + c;
        if (bias) {
            float4 bb = *(const float4*)(bias + col);
            v.x += bb.x; v.y += bb.y; v.z += bb.z; v.w += bb.w;
        }
        if (add) {
            float4 aa = *(const float4*)(add + row*(long)N + col);
            v.x += aa.x; v.y += aa.y; v.z += aa.z; v.w += aa.w;
        }
        *(float4*)(C + row*(long)N + col) = v;
    }
}

// ---------------- fused persistent GRU ----------------
// 1 launch, 235 blocks x 256 thr, 128 nodes/block, full 16-step recurrence.
// A (h) as bf16 hi/lo smem tiles; B (gWh permuted [384',128]) streamed from L2.
// x-projection precomputed into g_GX (permuted, bias included).
#define GRU_LDA 136
#define GRU_LDG 200
#define GRU_SMEM (128*GRU_LDA*2*2 + 128*GRU_LDG*4)   // 69632 + 102400 = 172032

__global__ void __launch_bounds__(256,1)
gru_fused(const __nv_bfloat16* __restrict__ Whh, const __nv_bfloat16* __restrict__ Whl)
{
    extern __shared__ char sm[];
    __nv_bfloat16* Ahi = (__nv_bfloat16*)sm;                  // [128][136]
    __nv_bfloat16* Alo = Ahi + 128*GRU_LDA;
    float* Gs = (float*)(sm + 128*GRU_LDA*2*2);               // [128][200]

    const int tid = threadIdx.x, wid = tid >> 5;
    const int wm = wid >> 2, wn = wid & 3;   // wm: 64-row half, wn: 48-col slice
    const long nb = (long)blockIdx.x * 128;

    for (int t = 0; t < TT; ++t) {
        // load h (t==0: zeros) and split to bf16 hi/lo
        // 128 rows x 16 groups of 8 cols = 2048 items = 256 thr x 8 iters
        #pragma unroll
        for (int i = 0; i < 8; ++i) {
            int li = tid + (i << 8);
            int r = li >> 4, c = (li & 15) << 3;
            long node = nb + r;
            float4 v0 = make_float4(0,0,0,0), v1 = make_float4(0,0,0,0);
            if (t > 0 && node < NN) {
                v0 = *(const float4*)(g_H + node*HE + c);
                v1 = *(const float4*)(g_H + node*HE + c + 4);
            }
            int o = r*GRU_LDA + c;
            float vv[8] = {v0.x,v0.y,v0.z,v0.w,v1.x,v1.y,v1.z,v1.w};
            #pragma unroll
            for (int q = 0; q < 8; ++q) {
                __nv_bfloat16 h = __float2bfloat16(vv[q]);
                Ahi[o+q] = h;
                Alo[o+q] = __float2bfloat16(vv[q] - __bfloat162float(h));
            }
        }
        __syncthreads();

        #pragma unroll
        for (int chunk = 0; chunk < 2; ++chunk) {
            FragC acc[4][3];
            #pragma unroll
            for (int mf = 0; mf < 4; ++mf)
                #pragma unroll
                for (int nf = 0; nf < 3; ++nf)
                    wmma::fill_fragment(acc[mf][nf], 0.f);

            for (int k0 = 0; k0 < HE; k0 += 16) {
                FragA ah[4], al[4];
                #pragma unroll
                for (int mf = 0; mf < 4; ++mf) {
                    int ro = (wm*64 + mf*16)*GRU_LDA + k0;
                    wmma::load_matrix_sync(ah[mf], Ahi + ro, GRU_LDA);
                    wmma::load_matrix_sync(al[mf], Alo + ro, GRU_LDA);
                }
                #pragma unroll
                for (int nf = 0; nf < 3; ++nf) {
                    int npp = chunk*192 + wn*48 + nf*16;
                    FragB bh, bl;
                    wmma::load_matrix_sync(bh, Whh + (long)npp*HE + k0, HE);
                    wmma::load_matrix_sync(bl, Whl + (long)npp*HE + k0, HE);
                    #pragma unroll
                    for (int mf = 0; mf < 4; ++mf) {
                        wmma::mma_sync(acc[mf][nf], ah[mf], bh, acc[mf][nf]);
                        wmma::mma_sync(acc[mf][nf], ah[mf], bl, acc[mf][nf]);
                        wmma::mma_sync(acc[mf][nf], al[mf], bh, acc[mf][nf]);
                    }
                }
            }
            #pragma unroll
            for (int mf = 0; mf < 4; ++mf)
                #pragma unroll
                for (int nf = 0; nf < 3; ++nf)
                    wmma::store_matrix_sync(Gs + (wm*64 + mf*16)*GRU_LDG + wn*48 + nf*16,
                                            acc[mf][nf], GRU_LDG, wmma::mem_row_major);
            __syncthreads();

            // gates for 64 j's in this chunk (128 rows x 64 = 8192 = 256 x 32)
            #pragma unroll
            for (int i = 0; i < 32; ++i) {
                int li = tid + (i << 8);
                int r = li >> 6, jl = li & 63;
                int jg = chunk*64 + jl;
                long node = nb + r;
                if (node < NN) {
                    const float* gsr = Gs + r*GRU_LDG + 3*jl;
                    float ghr = gsr[0] + g_gbhp[3*jg+0];
                    float ghz = gsr[1] + g_gbhp[3*jg+1];
                    float ghn = gsr[2] + g_gbhp[3*jg+2];
                    const float* gx = g_GX + (node*TT + t)*F3 + 3*jg;
                    float rr = sigf(gx[0] + ghr);
                    float zz = sigf(gx[1] + ghz);
                    float nn2 = tanhf(gx[2] + rr*ghn);
                    float hold = __bfloat162float(Ahi[r*GRU_LDA + jg]) +
                                 __bfloat162float(Alo[r*GRU_LDA + jg]);
                    g_H[node*HE + jg] = (1.f - zz)*nn2 + zz*hold;
                }
            }
            __syncthreads();
        }
    }
}

// ---------------- fused persistent LSTM decoder ----------------
// 1 launch, 94 blocks x 256 thr, 32 rows/block, 25 steps x 2 layers + out head.
// h0/h1 as persistent bf16 hi/lo smem tiles; c0/c1 in gmem (block-private).
// W0 = l0Wh permuted [1024'][256]; W1 = [l1Wx | l1Wh] packed [1024'][512].
#define DEC_LDA 264
#define DEC_LDG 1032
#define DEC_SMEM (32*DEC_LDA*2*4 + 32*DEC_LDG*4)  // 67584 + 132096 = 199680

__global__ void __launch_bounds__(256,1)
dec_fused(const __nv_bfloat16* __restrict__ W0h, const __nv_bfloat16* __restrict__ W0l,
          const __nv_bfloat16* __restrict__ W1h, const __nv_bfloat16* __restrict__ W1l,
          const float* __restrict__ opW, const float* __restrict__ opb,
          float* __restrict__ out)
{
    extern __shared__ char sm[];
    __nv_bfloat16* Ah0 = (__nv_bfloat16*)sm;          // [32][264]
    __nv_bfloat16* Al0 = Ah0 + 32*DEC_LDA;
    __nv_bfloat16* Ah1 = Al0 + 32*DEC_LDA;
    __nv_bfloat16* Al1 = Ah1 + 32*DEC_LDA;
    float* Gs = (float*)(sm + 32*DEC_LDA*2*4);        // [32][1032]

    const int tid = threadIdx.x, wid = tid >> 5;      // 8 warps, wn = wid
    const int bm = blockIdx.x * 32;

    // zero h tiles
    for (int i = tid; i < 4*32*DEC_LDA; i += 256)
        Ah0[i] = __float2bfloat16(0.f);
    __syncthreads();

    for (int t = 0; t < OUTL; ++t) {
        // ---------- layer 0: Gs = h0 @ W0^T (K=256) ----------
        {
            FragC acc[2][8];
            #pragma unroll
            for (int mf = 0; mf < 2; ++mf)
                #pragma unroll
                for (int nf = 0; nf < 8; ++nf)
                    wmma::fill_fragment(acc[mf][nf], 0.f);
            for (int k0 = 0; k0 < HD; k0 += 16) {
                FragA ah[2], al[2];
                #pragma unroll
                for (int mf = 0; mf < 2; ++mf) {
                    wmma::load_matrix_sync(ah[mf], Ah0 + (mf*16)*DEC_LDA + k0, DEC_LDA);
                    wmma::load_matrix_sync(al[mf], Al0 + (mf*16)*DEC_LDA + k0, DEC_LDA);
                }
                #pragma unroll
                for (int nf = 0; nf < 8; ++nf) {
                    int npp = wid*128 + nf*16;
                    FragB bh, bl;
                    wmma::load_matrix_sync(bh, W0h + (long)npp*HD + k0, HD);
                    wmma::load_matrix_sync(bl, W0l + (long)npp*HD + k0, HD);
                    #pragma unroll
                    for (int mf = 0; mf < 2; ++mf) {
                        wmma::mma_sync(acc[mf][nf], ah[mf], bh, acc[mf][nf]);
                        wmma::mma_sync(acc[mf][nf], ah[mf], bl, acc[mf][nf]);
                        wmma::mma_sync(acc[mf][nf], al[mf], bh, acc[mf][nf]);
                    }
                }
            }
            #pragma unroll
            for (int mf = 0; mf < 2; ++mf)
                #pragma unroll
                for (int nf = 0; nf < 8; ++nf)
                    wmma::store_matrix_sync(Gs + (mf*16)*DEC_LDG + wid*128 + nf*16,
                                            acc[mf][nf], DEC_LDG, wmma::mem_row_major);
        }
        __syncthreads();
        // l0 gates: quads are contiguous (permuted); X0 includes x-part + l0 bias
        #pragma unroll
        for (int i = 0; i < 32; ++i) {
            int li = tid + (i << 8);
            int r = li >> 8, j = li & 255;
            long row = bm + r;
            if (row < NT) {
                const float* gs = Gs + r*DEC_LDG + 4*j;
                const float* x0 = g_X0 + row*(4*HD) + 4*j;
                float ig = sigf(gs[0] + x0[0]);
                float fg = sigf(gs[1] + x0[1]);
                float gg = tanhf(gs[2] + x0[2]);
                float og = sigf(gs[3] + x0[3]);
                float c = (t == 0) ? 0.f : g_c0[row*HD + j];
                c = fg*c + ig*gg;
                g_c0[row*HD + j] = c;
                float h = og*tanhf(c);
                __nv_bfloat16 hh = __float2bfloat16(h);
                Ah0[r*DEC_LDA + j] = hh;
                Al0[r*DEC_LDA + j] = __float2bfloat16(h - __bfloat162float(hh));
            }
        }
        __syncthreads();

        // ---------- layer 1: Gs = [h0|h1] @ W1^T (K=512, packed weights) ----------
        {
            FragC acc[2][8];
            #pragma unroll
            for (int mf = 0; mf < 2; ++mf)
                #pragma unroll
                for (int nf = 0; nf < 8; ++nf)
                    wmma::fill_fragment(acc[mf][nf], 0.f);
            for (int k0 = 0; k0 < 2*HD; k0 += 16) {
                const __nv_bfloat16* Sh = (k0 < HD) ? Ah0 : Ah1;
                const __nv_bfloat16* Sl = (k0 < HD) ? Al0 : Al1;
                int kc = k0 & (HD-1);
                FragA ah[2], al[2];
                #pragma unroll
                for (int mf = 0; mf < 2; ++mf) {
                    wmma::load_matrix_sync(ah[mf], Sh + (mf*16)*DEC_LDA + kc, DEC_LDA);
                    wmma::load_matrix_sync(al[mf], Sl + (mf*16)*DEC_LDA + kc, DEC_LDA);
                }
                #pragma unroll
                for (int nf = 0; nf < 8; ++nf) {
                    int npp = wid*128 + nf*16;
                    FragB bh, bl;
                    wmma::load_matrix_sync(bh, W1h + (long)npp*(2*HD) + k0, 2*HD);
                    wmma::load_matrix_sync(bl, W1l + (long)npp*(2*HD) + k0, 2*HD);
                    #pragma unroll
                    for (int mf = 0; mf < 2; ++mf) {
                        wmma::mma_sync(acc[mf][nf], ah[mf], bh, acc[mf][nf]);
                        wmma::mma_sync(acc[mf][nf], ah[mf], bl, acc[mf][nf]);
                        wmma::mma_sync(acc[mf][nf], al[mf], bh, acc[mf][nf]);
                    }
                }
            }
            #pragma unroll
            for (int mf = 0; mf < 2; ++mf)
                #pragma unroll
                for (int nf = 0; nf < 8; ++nf)
                    wmma::store_matrix_sync(Gs + (mf*16)*DEC_LDG + wid*128 + nf*16,
                                            acc[mf][nf], DEC_LDG, wmma::mem_row_major);
        }
        __syncthreads();
        // l1 gates
        #pragma unroll
        for (int i = 0; i < 32; ++i) {
            int li = tid + (i << 8);
            int r = li >> 8, j = li & 255;
            long row = bm + r;
            if (row < NT) {
                const float* gs = Gs + r*DEC_LDG + 4*j;
                const float* bb = g_l1bp + 4*j;
                float ig = sigf(gs[0] + bb[0]);
                float fg = sigf(gs[1] + bb[1]);
                float gg = tanhf(gs[2] + bb[2]);
                float og = sigf(gs[3] + bb[3]);
                float c = (t == 0) ? 0.f : g_c1[row*HD + j];
                c = fg*c + ig*gg;
                g_c1[row*HD + j] = c;
                float h = og*tanhf(c);
                __nv_bfloat16 hh = __float2bfloat16(h);
                Ah1[r*DEC_LDA + j] = hh;
                Al1[r*DEC_LDA + j] = __float2bfloat16(h - __bfloat162float(hh));
            }
        }
        __syncthreads();

        // ---------- output head ----------
        {
            int r = tid >> 3, l8 = tid & 7;
            long row = bm + r;
            float s0 = 0.f, s1 = 0.f;
            #pragma unroll
            for (int k = l8; k < HD; k += 8) {
                float h = __bfloat162float(Ah1[r*DEC_LDA + k]) +
                          __bfloat162float(Al1[r*DEC_LDA + k]);
                s0 += h*opW[2*k];
                s1 += h*opW[2*k+1];
            }
            #pragma unroll
            for (int o = 4; o; o >>= 1) {
                s0 += __shfl_down_sync(0xffffffffu, s0, o, 8);
                s1 += __shfl_down_sync(0xffffffffu, s1, o, 8);
            }
            if (l8 == 0 && row < NT) {
                long base = (row*OUTL + t)*2;
                out[base]   = s0 + opb[0];
                out[base+1] = s1 + opb[1];
            }
        }
        __syncthreads();
    }
}

// ---------------- SIMT GEMM (small shapes: dyn, fc) ----------------
#define BM 64
#define BN 64
#define BK 16
#define SPAD 4

template<int PRE, int ACT>
__global__ void gemm_k(const float* __restrict__ A,  const float* __restrict__ W1, int Ka,
                       const float* __restrict__ bias, const int* __restrict__ rowidx,
                       float* __restrict__ C, int M, int N)
{
    __shared__ float As[BK][BM+SPAD];
    __shared__ float Ws[BK][BN+SPAD];
    const int bm = blockIdx.y * BM, bn = blockIdx.x * BN;
    const int tid = threadIdx.x;
    const int tx = tid & 15, ty = tid >> 4;

    float acc[4][4] = {};

    const int ar = tid >> 2;
    const int ak = (tid & 3) << 2;
    const int wk = tid >> 4;
    const int wn = (tid & 15) << 2;

    const int arow_g = bm + ar;
    long arow = -1;
    if (arow_g < M) arow = rowidx ? (long)rowidx[arow_g] : (long)arow_g;

    for (int k0 = 0; k0 < Ka; k0 += BK) {
        float4 av = make_float4(0.f,0.f,0.f,0.f);
        if (arow >= 0) av = *(const float4*)(A + arow*(long)Ka + k0 + ak);
        if (PRE) { av.x=lk01(av.x); av.y=lk01(av.y); av.z=lk01(av.z); av.w=lk01(av.w); }
        As[ak  ][ar] = av.x;
        As[ak+1][ar] = av.y;
        As[ak+2][ar] = av.z;
        As[ak+3][ar] = av.w;
        float4 wv = *(const float4*)(W1 + (long)(k0+wk)*N + bn + wn);
        *(float4*)&Ws[wk][wn] = wv;
        __syncthreads();
        #pragma unroll
        for (int k = 0; k < BK; ++k) {
            float4 a4 = *(const float4*)&As[k][ty<<2];
            float4 b4 = *(const float4*)&Ws[k][tx<<2];
            acc[0][0]+=a4.x*b4.x; acc[0][1]+=a4.x*b4.y; acc[0][2]+=a4.x*b4.z; acc[0][3]+=a4.x*b4.w;
            acc[1][0]+=a4.y*b4.x; acc[1][1]+=a4.y*b4.y; acc[1][2]+=a4.y*b4.z; acc[1][3]+=a4.y*b4.w;
            acc[2][0]+=a4.z*b4.x; acc[2][1]+=a4.z*b4.y; acc[2][2]+=a4.z*b4.z; acc[2][3]+=a4.z*b4.w;
            acc[3][0]+=a4.w*b4.x; acc[3][1]+=a4.w*b4.y; acc[3][2]+=a4.w*b4.z; acc[3][3]+=a4.w*b4.w;
        }
        __syncthreads();
    }

    #pragma unroll
    for (int i = 0; i < 4; ++i) {
        int row = bm + (ty<<2) + i;
        if (row >= M) continue;
        #pragma unroll
        for (int j = 0; j < 4; ++j) {
            int col = bn + (tx<<2) + j;
            float v = acc[i][j];
            if (bias) v += bias[col];
            if (ACT == 1) v = lk01(v);
            C[(long)row*N + col] = v;
        }
    }
}

// ---------------- encoder embedding ----------------
__global__ void emb_kernel(const float* __restrict__ x, const float* __restrict__ ipW,
                           const float* __restrict__ ipb)
{
    long i = (long)blockIdx.x*blockDim.x + threadIdx.x;
    if (i >= (long)NN*TT*DE) return;
    long row = i >> 5; int j = (int)(i & 31);
    float v = x[row*2]*ipW[j] + x[row*2+1]*ipW[DE+j] + ipb[j];
    g_EMB[i] = lk01(v);
}

// ---------------- CSR build ----------------
__global__ void edge_count(const int* __restrict__ ei){
    int e = blockIdx.x*blockDim.x + threadIdx.x;
    if (e >= NE) return;
    int d = (e < NE0) ? ei[NE0+e] : (e - NE0);
    atomicAdd(&g_cnt[d], 1);
}
__global__ void scan_kernel(){
    __shared__ int sh[1024];
    __shared__ int run;
    int tid = threadIdx.x;
    if (tid == 0) run = 0;
    __syncthreads();
    for (int base = 0; base < NN; base += 1024) {
        int v = (base + tid < NN) ? g_cnt[base + tid] : 0;
        sh[tid] = v; __syncthreads();
        for (int off = 1; off < 1024; off <<= 1) {
            int tv = (tid >= off) ? sh[tid-off] : 0;
            __syncthreads();
            sh[tid] += tv;
            __syncthreads();
        }
        if (base + tid < NN) g_offs[base + tid + 1] = run + sh[tid];
        __syncthreads();
        if (tid == 0) run += sh[1023];
        __syncthreads();
    }
    if (tid == 0) g_offs[0] = 0;
}
__global__ void copy_cur(){
    int i = blockIdx.x*blockDim.x + threadIdx.x;
    if (i < NN) g_cur[i] = g_offs[i];
}
__global__ void edge_scatter(const int* __restrict__ ei){
    int e = blockIdx.x*blockDim.x + threadIdx.x;
    if (e >= NE) return;
    int s, d;
    if (e < NE0) { s = ei[e]; d = ei[NE0+e]; } else { s = e - NE0; d = s; }
    int pos = atomicAdd(&g_cur[d], 1);
    g_ssrc[pos] = s;
}

// ---------------- GAT ----------------
__global__ void attn_coef(const float* __restrict__ F, const float* __restrict__ a_s,
                          const float* __restrict__ a_d)
{
    int w = (blockIdx.x*blockDim.x + threadIdx.x) >> 5;
    if (w >= NN*3) return;
    int lane = threadIdx.x & 31;
    int node = w / 3, h = w - node*3;
    const float* f = F + (long)node*F3 + h*HE;
    const float* As_ = a_s + h*HE;
    const float* Ad_ = a_d + h*HE;
    float s1 = 0.f, s2 = 0.f;
    #pragma unroll
    for (int c = lane; c < HE; c += 32) { float fv = f[c]; s1 += fv*As_[c]; s2 += fv*Ad_[c]; }
    #pragma unroll
    for (int o = 16; o; o >>= 1) {
        s1 += __shfl_down_sync(0xffffffffu, s1, o);
        s2 += __shfl_down_sync(0xffffffffu, s2, o);
    }
    if (lane == 0) { g_asv[w] = s1; g_adv[w] = s2; }
}

__global__ void gat_agg(const float* __restrict__ F, const float* __restrict__ bias,
                        float* __restrict__ O)
{
    int w = (blockIdx.x*blockDim.x + threadIdx.x) >> 5;
    if (w >= NN) return;
    int lane = threadIdx.x & 31;
    int beg = g_offs[w], end = g_offs[w+1];
    float ad0 = g_adv[w*3], ad1 = g_adv[w*3+1], ad2 = g_adv[w*3+2];
    float m0 = -1e30f, m1 = -1e30f, m2 = -1e30f;
    float d0 = 0.f, d1 = 0.f, d2 = 0.f;
    float acc[12];
    #pragma unroll
    for (int q = 0; q < 12; ++q) acc[q] = 0.f;

    for (int p = beg; p < end; ++p) {
        int s = g_ssrc[p];
        float e0 = g_asv[s*3]   + ad0; e0 = (e0 >= 0.f) ? e0 : 0.2f*e0;
        float e1 = g_asv[s*3+1] + ad1; e1 = (e1 >= 0.f) ? e1 : 0.2f*e1;
        float e2 = g_asv[s*3+2] + ad2; e2 = (e2 >= 0.f) ? e2 : 0.2f*e2;
        const float* f = F + (long)s*F3;
        {
            float nm = fmaxf(m0, e0); float sc = __expf(m0-nm); float wv = __expf(e0-nm);
            d0 = d0*sc + wv;
            #pragma unroll
            for (int q = 0; q < 4; ++q) acc[q] = acc[q]*sc + wv*f[q*32 + lane];
            m0 = nm;
        }
        {
            float nm = fmaxf(m1, e1); float sc = __expf(m1-nm); float wv = __expf(e1-nm);
            d1 = d1*sc + wv;
            #pragma unroll
            for (int q = 0; q < 4; ++q) acc[4+q] = acc[4+q]*sc + wv*f[HE + q*32 + lane];
            m1 = nm;
        }
        {
            float nm = fmaxf(m2, e2); float sc = __expf(m2-nm); float wv = __expf(e2-nm);
            d2 = d2*sc + wv;
            #pragma unroll
            for (int q = 0; q < 4; ++q) acc[8+q] = acc[8+q]*sc + wv*f[2*HE + q*32 + lane];
            m2 = nm;
        }
    }
    float* o = O + (long)w*F3;
    #pragma unroll
    for (int q = 0; q < 4; ++q) {
        int c0 = q*32 + lane;
        o[c0]        = acc[q]  /d0 + bias[c0];
        o[HE + c0]   = acc[4+q]/d1 + bias[HE + c0];
        o[2*HE + c0] = acc[8+q]/d2 + bias[2*HE + c0];
    }
}

// ---------------- host orchestration ----------------
static inline void mmagemm(const float* A, const __nv_bfloat16* Wh, const __nv_bfloat16* Wl, int K,
                           const float* bias, const float* add, float* C, long M, int N)
{
    dim3 g(N/WBN, (unsigned)((M + WBM - 1)/WBM));
    mma_gemm<<<g, 256, MMA_SMEM>>>(A, Wh, Wl, K, bias, add, C, (int)M, N);
}

extern "C" void kernel_launch(void* const* d_in, const int* in_sizes, int n_in,
                              void* d_out, int out_size)
{
    const float* x    = (const float*)d_in[0];
    const int*   ei   = (const int*)  d_in[1];
    const int*   tgt  = (const int*)  d_in[2];
    const float* ipW  = (const float*)d_in[3];
    const float* ipb  = (const float*)d_in[4];
    const float* gWx  = (const float*)d_in[5];
    const float* gWh  = (const float*)d_in[6];
    const float* gbx  = (const float*)d_in[7];
    const float* gbh  = (const float*)d_in[8];
    const float* dynW = (const float*)d_in[9];
    const float* dynb = (const float*)d_in[10];
    const float* g1W  = (const float*)d_in[11];
    const float* g1as = (const float*)d_in[12];
    const float* g1ad = (const float*)d_in[13];
    const float* g1b  = (const float*)d_in[14];
    const float* g2W  = (const float*)d_in[15];
    const float* g2as = (const float*)d_in[16];
    const float* g2ad = (const float*)d_in[17];
    const float* g2b  = (const float*)d_in[18];
    const float* fcW  = (const float*)d_in[19];
    const float* fcb  = (const float*)d_in[20];
    const float* l0Wx = (const float*)d_in[21];
    const float* l0Wh = (const float*)d_in[22];
    const float* l0b  = (const float*)d_in[23];
    const float* l1Wx = (const float*)d_in[24];
    const float* l1Wh = (const float*)d_in[25];
    const float* l1b  = (const float*)d_in[26];
    const float* opW  = (const float*)d_in[27];
    const float* opb  = (const float*)d_in[28];
    float* out = (float*)d_out;
    (void)in_sizes; (void)n_in; (void)out_size;

    float *EMB,*GX,*H,*HENC,*F1,*O1,*F2,*O2,*ENC,*X0;
    float *gbxp,*gbhp,*l0bp,*l1bp;
    __nv_bfloat16 *WTh,*WTl;
    cudaGetSymbolAddress((void**)&EMB,  g_EMB);
    cudaGetSymbolAddress((void**)&GX,   g_GX);
    cudaGetSymbolAddress((void**)&H,    g_H);
    cudaGetSymbolAddress((void**)&HENC, g_HENC);
    cudaGetSymbolAddress((void**)&F1,   g_F1);
    cudaGetSymbolAddress((void**)&O1,   g_O1);
    cudaGetSymbolAddress((void**)&F2,   g_F2);
    cudaGetSymbolAddress((void**)&O2,   g_O2);
    cudaGetSymbolAddress((void**)&ENC,  g_ENC);
    cudaGetSymbolAddress((void**)&X0,   g_X0);
    cudaGetSymbolAddress((void**)&gbxp, g_gbxp);
    cudaGetSymbolAddress((void**)&gbhp, g_gbhp);
    cudaGetSymbolAddress((void**)&l0bp, g_l0bp);
    cudaGetSymbolAddress((void**)&l1bp, g_l1bp);
    cudaGetSymbolAddress((void**)&WTh,  g_WThi);
    cudaGetSymbolAddress((void**)&WTl,  g_WTlo);
    int *cntp;
    cudaGetSymbolAddress((void**)&cntp, g_cnt);

    static int attr_set = 0;
    if (!attr_set) {
        cudaFuncSetAttribute(gru_fused, cudaFuncAttributeMaxDynamicSharedMemorySize, GRU_SMEM);
        cudaFuncSetAttribute(dec_fused, cudaFuncAttributeMaxDynamicSharedMemorySize, DEC_SMEM);
        attr_set = 1;
    }

    // weight offsets (elements)
    const int o_gWx  = 0;                      // [384'][32]
    const int o_gWh  = 12288;                  // [384'][128]
    const int o_g1W  = 61440;                  // [384][128]
    const int o_g2W  = 110592;                 // [384][384]
    const int o_l0Wx = 258048;                 // [1024'][128]
    const int o_l0Wh = 389120;                 // [1024'][256]
    const int o_l1   = 651264;                 // [1024'][512] = [l1Wx | l1Wh] packed

    // ---- weight prep (permuted + packed for recurrent layers) ----
    wsplitp<<<(32*384+255)/256,256>>>(gWx,  WTh+o_gWx,  WTl+o_gWx,  32, 384, 3, 32, 0);
    wsplitp<<<(128*384+255)/256,256>>>(gWh,  WTh+o_gWh,  WTl+o_gWh,  128, 384, 3, 128, 0);
    wsplitp<<<(128*384+255)/256,256>>>(g1W,  WTh+o_g1W,  WTl+o_g1W,  128, 384, 1, 128, 0);
    wsplitp<<<(384*384+255)/256,256>>>(g2W,  WTh+o_g2W,  WTl+o_g2W,  384, 384, 1, 384, 0);
    wsplitp<<<(128*1024+255)/256,256>>>(l0Wx, WTh+o_l0Wx, WTl+o_l0Wx, 128, 1024, 4, 128, 0);
    wsplitp<<<(256*1024+255)/256,256>>>(l0Wh, WTh+o_l0Wh, WTl+o_l0Wh, 256, 1024, 4, 256, 0);
    wsplitp<<<(256*1024+255)/256,256>>>(l1Wx, WTh+o_l1,   WTl+o_l1,   256, 1024, 4, 512, 0);
    wsplitp<<<(256*1024+255)/256,256>>>(l1Wh, WTh+o_l1,   WTl+o_l1,   256, 1024, 4, 512, 256);
    bperm<<<2,256>>>(gbx, gbxp, 384, 3);
    bperm<<<2,256>>>(gbh, gbhp, 384, 3);
    bperm<<<4,256>>>(l0b, l0bp, 1024, 4);
    bperm<<<4,256>>>(l1b, l1bp, 1024, 4);

    // ---- CSR build ----
    zero_i<<<(NN+255)/256,256>>>(cntp, NN);
    edge_count<<<(NE+255)/256,256>>>(ei);
    scan_kernel<<<1,1024>>>();
    copy_cur<<<(NN+255)/256,256>>>();
    edge_scatter<<<(NE+255)/256,256>>>(ei);

    // ---- encoder ----
    emb_kernel<<<(int)(((long)NN*TT*DE + 255)/256),256>>>(x, ipW, ipb);
    // GX = EMB @ gWx (permuted) + gbx (permuted), all timesteps at once
    mmagemm(EMB, WTh+o_gWx, WTl+o_gWx, 32, gbxp, nullptr, GX, (long)NN*TT, F3);
    // fused 16-step GRU
    gru_fused<<<(NN+127)/128, 256, GRU_SMEM>>>(WTh+o_gWh, WTl+o_gWh);
    // hist_enc = leaky( leaky(H) @ dynW + dynb )
    {
        dim3 g(HE/BN, (NN+BM-1)/BM);
        gemm_k<1,1><<<g,256>>>(H, dynW, HE, dynb, nullptr, HENC, NN, HE);
    }

    // ---- GAT layer 1 ----
    mmagemm(HENC, WTh+o_g1W, WTl+o_g1W, HE, nullptr, nullptr, F1, NN, F3);
    attn_coef<<<(NN*3*32+255)/256,256>>>(F1, g1as, g1ad);
    gat_agg<<<(NN*32+255)/256,256>>>(F1, g1b, O1);

    // ---- GAT layer 2 ----
    mmagemm(O1, WTh+o_g2W, WTl+o_g2W, F3, nullptr, nullptr, F2, NN, F3);
    attn_coef<<<(NN*3*32+255)/256,256>>>(F2, g2as, g2ad);
    gat_agg<<<(NN*32+255)/256,256>>>(F2, g2b, O2);

    // ---- target gather + fc ----
    {
        dim3 g(HE/BN, (NT+BM-1)/BM);
        gemm_k<0,1><<<g,256>>>(O2, fcW, F3, fcb, tgt, ENC, NT, HE);
    }

    // ---- decoder: X0 (permuted, incl l0 bias) then fused 25-step LSTM ----
    mmagemm(ENC, WTh+o_l0Wx, WTl+o_l0Wx, HE, l0bp, nullptr, X0, NT, 4*HD);
    dec_fused<<<(NT+31)/32, 256, DEC_SMEM>>>(WTh+o_l0Wh, WTl+o_l0Wh,
                                             WTh+o_l1,   WTl+o_l1,
                                             opW, opb, out);
}

// round 9
// speedup vs baseline: 1.3797x; 1.3797x over previous
#include <cuda_runtime.h>
#include <cuda_bf16.h>
#include <mma.h>
#include <math.h>
#include <stdint.h>

using namespace nvcuda;

#define NN   30000
#define TT   16
#define DE   32
#define HE   128
#define F3   384
#define NE0  300000
#define NE   330000
#define NT   3000
#define HD   256
#define OUTL 25

// ---------------- scratch ----------------
__device__ __align__(256) float g_EMB[NN*TT*DE];
__device__ __align__(256) float g_GX[(long)NN*TT*F3];   // permuted x-projection
__device__ __align__(256) float g_H[NN*HE];
__device__ __align__(256) float g_H2[NN*HE];
__device__ __align__(256) float g_HENC[NN*HE];
__device__ __align__(256) float g_F1[NN*F3];
__device__ __align__(256) float g_O1[NN*F3];
__device__ __align__(256) float g_F2[NN*F3];
__device__ __align__(256) float g_O2[NN*F3];
__device__ __align__(256) float g_asv[NN*3];
__device__ __align__(256) float g_adv[NN*3];
__device__ __align__(256) float g_ENC[NT*HE];
__device__ __align__(256) float g_X0[NT*4*HD];          // permuted, incl l0 bias
__device__ __align__(256) float g_c0[NT*HD];
__device__ __align__(256) float g_c1[NT*HD];
__device__ __align__(256) float g_h0a[NT*HD];
__device__ __align__(256) float g_h0b[NT*HD];
__device__ __align__(256) float g_h1a[NT*HD];
__device__ __align__(256) float g_h1b[NT*HD];
__device__ int g_cnt[NN];
__device__ int g_offs[NN+1];
__device__ int g_cur[NN];
__device__ int g_ssrc[NE];
__device__ float g_gbxp[F3];
__device__ float g_gbhp[F3];
__device__ float g_l0bp[4*HD];
__device__ float g_l1bp[4*HD];
#define WT_TOTAL 1200000
__device__ __align__(256) __nv_bfloat16 g_WThi[WT_TOTAL];
__device__ __align__(256) __nv_bfloat16 g_WTlo[WT_TOTAL];

__device__ __forceinline__ float sigf(float x){ return 1.f/(1.f+__expf(-x)); }
__device__ __forceinline__ float lk01(float x){ return x>=0.f? x : 0.1f*x; }

// ---------------- utility ----------------
__global__ void zero_f(float* __restrict__ p, long n){
    long i = (long)blockIdx.x*blockDim.x + threadIdx.x;
    if (i < n) p[i] = 0.f;
}
__global__ void zero_i(int* __restrict__ p, int n){
    int i = blockIdx.x*blockDim.x + threadIdx.x;
    if (i < n) p[i] = 0;
}

// W[K,N] fp32 -> bf16 hi/lo at [np*ldk + kofs + k], np = (n % (N/P))*P + n/(N/P)
__global__ void wsplitp(const float* __restrict__ W, __nv_bfloat16* __restrict__ hi,
                        __nv_bfloat16* __restrict__ lo, int K, int N, int P,
                        int ldk, int kofs)
{
    int idx = blockIdx.x*blockDim.x + threadIdx.x;
    if (idx >= K*N) return;
    int k = idx / N, n = idx - k*N;
    int Gp = N / P;
    int np = (n % Gp)*P + n/Gp;
    float v = W[idx];
    __nv_bfloat16 h = __float2bfloat16(v);
    hi[(long)np*ldk + kofs + k] = h;
    lo[(long)np*ldk + kofs + k] = __float2bfloat16(v - __bfloat162float(h));
}

__global__ void bperm(const float* __restrict__ b, float* __restrict__ bp, int N, int P)
{
    int n = blockIdx.x*blockDim.x + threadIdx.x;
    if (n >= N) return;
    int Gp = N / P;
    bp[(n % Gp)*P + n/Gp] = b[n];
}

typedef wmma::fragment<wmma::matrix_a, 16,16,16, __nv_bfloat16, wmma::row_major> FragA;
typedef wmma::fragment<wmma::matrix_b, 16,16,16, __nv_bfloat16, wmma::col_major> FragB;
typedef wmma::fragment<wmma::accumulator, 16,16,16, float> FragC;

// ---------------- generic WMMA bf16x3 GEMM (GX, GAT, X0) ----------------
#define WBM 128
#define WBN 64
#define WBK 32
#define SKA 40
#define SKB 40
#define SCC 72
#define MMA_SMEM 36864

__global__ void __launch_bounds__(256,2)
mma_gemm(const float* __restrict__ A1, const __nv_bfloat16* __restrict__ W1h,
         const __nv_bfloat16* __restrict__ W1l, int K1,
         const float* __restrict__ bias,
         float* __restrict__ C, int M, int N)
{
    extern __shared__ char smc[];
    __nv_bfloat16* Ah = (__nv_bfloat16*)smc;
    __nv_bfloat16* Al = Ah + WBM*SKA;
    __nv_bfloat16* Bh = Al + WBM*SKA;
    __nv_bfloat16* Bl = Bh + WBN*SKB;
    float* Cs = (float*)smc;

    const int tid = threadIdx.x, wid = tid >> 5;
    const int warp_m = wid >> 1, warp_n = wid & 1;
    const long bm = (long)blockIdx.y * WBM;
    const int bn = blockIdx.x * WBN;

    FragC acc[2][2];
    #pragma unroll
    for (int mm = 0; mm < 2; ++mm)
        #pragma unroll
        for (int nn = 0; nn < 2; ++nn)
            wmma::fill_fragment(acc[mm][nn], 0.f);

    for (int k0 = 0; k0 < K1; k0 += WBK) {
        #pragma unroll
        for (int i = 0; i < 4; ++i) {
            int li = tid + (i << 8);
            int r = li >> 3, c = (li & 7) << 2;
            float4 v = make_float4(0.f,0.f,0.f,0.f);
            if (bm + r < M) v = *(const float4*)(A1 + (bm+r)*K1 + k0 + c);
            __nv_bfloat16 hx = __float2bfloat16(v.x);
            __nv_bfloat16 hy = __float2bfloat16(v.y);
            __nv_bfloat16 hz = __float2bfloat16(v.z);
            __nv_bfloat16 hw = __float2bfloat16(v.w);
            int o = r*SKA + c;
            Ah[o]   = hx; Ah[o+1] = hy; Ah[o+2] = hz; Ah[o+3] = hw;
            Al[o]   = __float2bfloat16(v.x - __bfloat162float(hx));
            Al[o+1] = __float2bfloat16(v.y - __bfloat162float(hy));
            Al[o+2] = __float2bfloat16(v.z - __bfloat162float(hz));
            Al[o+3] = __float2bfloat16(v.w - __bfloat162float(hw));
        }
        {
            int r = tid >> 2, c = (tid & 3) << 3;
            long go = (long)(bn + r)*K1 + k0 + c;
            *(uint4*)&Bh[r*SKB + c] = *(const uint4*)(W1h + go);
            *(uint4*)&Bl[r*SKB + c] = *(const uint4*)(W1l + go);
        }
        __syncthreads();

        #pragma unroll
        for (int kk = 0; kk < WBK; kk += 16) {
            FragA ah[2], al[2];
            FragB bh[2], bl[2];
            #pragma unroll
            for (int mm = 0; mm < 2; ++mm) {
                int ro = (warp_m*32 + mm*16)*SKA + kk;
                wmma::load_matrix_sync(ah[mm], Ah + ro, SKA);
                wmma::load_matrix_sync(al[mm], Al + ro, SKA);
            }
            #pragma unroll
            for (int nn = 0; nn < 2; ++nn) {
                int no = (warp_n*32 + nn*16)*SKB + kk;
                wmma::load_matrix_sync(bh[nn], Bh + no, SKB);
                wmma::load_matrix_sync(bl[nn], Bl + no, SKB);
            }
            #pragma unroll
            for (int mm = 0; mm < 2; ++mm)
                #pragma unroll
                for (int nn = 0; nn < 2; ++nn) {
                    wmma::mma_sync(acc[mm][nn], ah[mm], bh[nn], acc[mm][nn]);
                    wmma::mma_sync(acc[mm][nn], ah[mm], bl[nn], acc[mm][nn]);
                    wmma::mma_sync(acc[mm][nn], al[mm], bh[nn], acc[mm][nn]);
                }
        }
        __syncthreads();
    }

    #pragma unroll
    for (int mm = 0; mm < 2; ++mm)
        #pragma unroll
        for (int nn = 0; nn < 2; ++nn)
            wmma::store_matrix_sync(Cs + (warp_m*32 + mm*16)*SCC + warp_n*32 + nn*16,
                                    acc[mm][nn], SCC, wmma::mem_row_major);
    __syncthreads();

    #pragma unroll
    for (int i = 0; i < 8; ++i) {
        int li = tid + (i << 8);
        int r = li >> 4, c = (li & 15) << 2;
        long row = bm + r;
        if (row >= M) continue;
        float4 v = *(float4*)&Cs[r*SCC + c];
        int col = bn + c;
        if (bias) {
            float4 bb = *(const float4*)(bias + col);
            v.x += bb.x; v.y += bb.y; v.z += bb.z; v.w += bb.w;
        }
        *(float4*)(C + row*(long)N + col) = v;
    }
}

// ---------------- GRU step GEMM with fused gates ----------------
// C tile 128x96 of Hin @ Wh^T (permuted triples); epilogue: GRU gate -> Hout.
#define GLDC 100
#define GRU_SMEM 51200

__global__ void __launch_bounds__(256,2)
gru_step(const float* __restrict__ Hin, const __nv_bfloat16* __restrict__ Wh,
         const __nv_bfloat16* __restrict__ Wl, float* __restrict__ Hout, int t)
{
    extern __shared__ char sm[];
    __nv_bfloat16* Ah = (__nv_bfloat16*)sm;           // [128][40]
    __nv_bfloat16* Al = Ah + 128*SKA;
    __nv_bfloat16* Bh = Al + 128*SKA;                 // [96][40]
    __nv_bfloat16* Bl = Bh + 96*SKB;
    float* Cs = (float*)sm;                           // [128][100]

    const int tid = threadIdx.x, wid = tid >> 5;
    const int warp_m = wid >> 1, warp_n = wid & 1;    // 4m x 2n, warp tile 32x48
    const long bm = (long)blockIdx.y * 128;
    const int bn = blockIdx.x * 96;

    FragC acc[2][3];
    #pragma unroll
    for (int mf = 0; mf < 2; ++mf)
        #pragma unroll
        for (int nf = 0; nf < 3; ++nf)
            wmma::fill_fragment(acc[mf][nf], 0.f);

    for (int k0 = 0; k0 < HE; k0 += WBK) {
        #pragma unroll
        for (int i = 0; i < 4; ++i) {
            int li = tid + (i << 8);
            int r = li >> 3, c = (li & 7) << 2;
            float4 v = make_float4(0.f,0.f,0.f,0.f);
            if (bm + r < NN) v = *(const float4*)(Hin + (bm+r)*HE + k0 + c);
            __nv_bfloat16 hx = __float2bfloat16(v.x);
            __nv_bfloat16 hy = __float2bfloat16(v.y);
            __nv_bfloat16 hz = __float2bfloat16(v.z);
            __nv_bfloat16 hw = __float2bfloat16(v.w);
            int o = r*SKA + c;
            Ah[o]   = hx; Ah[o+1] = hy; Ah[o+2] = hz; Ah[o+3] = hw;
            Al[o]   = __float2bfloat16(v.x - __bfloat162float(hx));
            Al[o+1] = __float2bfloat16(v.y - __bfloat162float(hy));
            Al[o+2] = __float2bfloat16(v.z - __bfloat162float(hz));
            Al[o+3] = __float2bfloat16(v.w - __bfloat162float(hw));
        }
        #pragma unroll
        for (int i = 0; i < 2; ++i) {
            int li = tid + (i << 8);
            if (li < 384) {
                int r = li >> 2, c = (li & 3) << 3;
                long go = (long)(bn + r)*HE + k0 + c;
                *(uint4*)&Bh[r*SKB + c] = *(const uint4*)(Wh + go);
                *(uint4*)&Bl[r*SKB + c] = *(const uint4*)(Wl + go);
            }
        }
        __syncthreads();

        #pragma unroll
        for (int kk = 0; kk < WBK; kk += 16) {
            FragA ah[2], al[2];
            #pragma unroll
            for (int mf = 0; mf < 2; ++mf) {
                int ro = (warp_m*32 + mf*16)*SKA + kk;
                wmma::load_matrix_sync(ah[mf], Ah + ro, SKA);
                wmma::load_matrix_sync(al[mf], Al + ro, SKA);
            }
            #pragma unroll
            for (int nf = 0; nf < 3; ++nf) {
                int no = (warp_n*48 + nf*16)*SKB + kk;
                FragB bh, bl;
                wmma::load_matrix_sync(bh, Bh + no, SKB);
                wmma::load_matrix_sync(bl, Bl + no, SKB);
                #pragma unroll
                for (int mf = 0; mf < 2; ++mf) {
                    wmma::mma_sync(acc[mf][nf], ah[mf], bh, acc[mf][nf]);
                    wmma::mma_sync(acc[mf][nf], ah[mf], bl, acc[mf][nf]);
                    wmma::mma_sync(acc[mf][nf], al[mf], bh, acc[mf][nf]);
                }
            }
        }
        __syncthreads();
    }

    #pragma unroll
    for (int mf = 0; mf < 2; ++mf)
        #pragma unroll
        for (int nf = 0; nf < 3; ++nf)
            wmma::store_matrix_sync(Cs + (warp_m*32 + mf*16)*GLDC + warp_n*48 + nf*16,
                                    acc[mf][nf], GLDC, wmma::mem_row_major);
    __syncthreads();

    // gate epilogue: 128 rows x 32 triples
    #pragma unroll
    for (int i = 0; i < 16; ++i) {
        int li = tid + (i << 8);
        int r = li >> 5, q = li & 31;
        long node = bm + r;
        if (node < NN) {
            int jg = blockIdx.x*32 + q;
            const float* gsr = Cs + r*GLDC + 3*q;
            float ghr = gsr[0] + g_gbhp[3*jg+0];
            float ghz = gsr[1] + g_gbhp[3*jg+1];
            float ghn = gsr[2] + g_gbhp[3*jg+2];
            const float* gx = g_GX + (node*TT + t)*F3 + 3*jg;
            float rr = sigf(gx[0] + ghr);
            float zz = sigf(gx[1] + ghz);
            float nn2 = tanhf(gx[2] + rr*ghn);
            float hold = Hin[node*HE + jg];
            Hout[node*HE + jg] = (1.f - zz)*nn2 + zz*hold;
        }
    }
}

// ---------------- decoder step GEMM with fused LSTM gates ----------------
// L1=0: Gs = h0 @ W0^T (K=256), pre = X0 row quads; L1=1: Gs = [h0|h1] @ W1^T (K=512), pre = bias.
template<int L1>
__global__ void __launch_bounds__(256,2)
dec_gemm(const float* __restrict__ A1, const float* __restrict__ A2,
         const __nv_bfloat16* __restrict__ Wh, const __nv_bfloat16* __restrict__ Wl,
         const float* __restrict__ pre, float* __restrict__ cbuf,
         float* __restrict__ hout, int first)
{
    extern __shared__ char sm[];
    __nv_bfloat16* Ah = (__nv_bfloat16*)sm;           // [128][40]
    __nv_bfloat16* Al = Ah + 128*SKA;
    __nv_bfloat16* Bh = Al + 128*SKA;                 // [64][40]
    __nv_bfloat16* Bl = Bh + 64*SKB;
    float* Cs = (float*)sm;                           // [128][68]

    const int tid = threadIdx.x, wid = tid >> 5;
    const int warp_m = wid >> 1, warp_n = wid & 1;
    const long bm = (long)blockIdx.y * 128;
    const int bn = blockIdx.x * 64;
    const int KTOT = L1 ? 2*HD : HD;

    FragC acc[2][2];
    #pragma unroll
    for (int mm = 0; mm < 2; ++mm)
        #pragma unroll
        for (int nn = 0; nn < 2; ++nn)
            wmma::fill_fragment(acc[mm][nn], 0.f);

    for (int k0 = 0; k0 < KTOT; k0 += WBK) {
        const float* A = (L1 && k0 >= HD) ? A2 : A1;
        const int ka = k0 & (HD-1);
        #pragma unroll
        for (int i = 0; i < 4; ++i) {
            int li = tid + (i << 8);
            int r = li >> 3, c = (li & 7) << 2;
            float4 v = make_float4(0.f,0.f,0.f,0.f);
            if (bm + r < NT) v = *(const float4*)(A + (bm+r)*HD + ka + c);
            __nv_bfloat16 hx = __float2bfloat16(v.x);
            __nv_bfloat16 hy = __float2bfloat16(v.y);
            __nv_bfloat16 hz = __float2bfloat16(v.z);
            __nv_bfloat16 hw = __float2bfloat16(v.w);
            int o = r*SKA + c;
            Ah[o]   = hx; Ah[o+1] = hy; Ah[o+2] = hz; Ah[o+3] = hw;
            Al[o]   = __float2bfloat16(v.x - __bfloat162float(hx));
            Al[o+1] = __float2bfloat16(v.y - __bfloat162float(hy));
            Al[o+2] = __float2bfloat16(v.z - __bfloat162float(hz));
            Al[o+3] = __float2bfloat16(v.w - __bfloat162float(hw));
        }
        {
            int r = tid >> 2, c = (tid & 3) << 3;
            long go = (long)(bn + r)*KTOT + k0 + c;
            *(uint4*)&Bh[r*SKB + c] = *(const uint4*)(Wh + go);
            *(uint4*)&Bl[r*SKB + c] = *(const uint4*)(Wl + go);
        }
        __syncthreads();

        #pragma unroll
        for (int kk = 0; kk < WBK; kk += 16) {
            FragA ah[2], al[2];
            FragB bh[2], bl[2];
            #pragma unroll
            for (int mm = 0; mm < 2; ++mm) {
                int ro = (warp_m*32 + mm*16)*SKA + kk;
                wmma::load_matrix_sync(ah[mm], Ah + ro, SKA);
                wmma::load_matrix_sync(al[mm], Al + ro, SKA);
            }
            #pragma unroll
            for (int nn = 0; nn < 2; ++nn) {
                int no = (warp_n*32 + nn*16)*SKB + kk;
                wmma::load_matrix_sync(bh[nn], Bh + no, SKB);
                wmma::load_matrix_sync(bl[nn], Bl + no, SKB);
            }
            #pragma unroll
            for (int mm = 0; mm < 2; ++mm)
                #pragma unroll
                for (int nn = 0; nn < 2; ++nn) {
                    wmma::mma_sync(acc[mm][nn], ah[mm], bh[nn], acc[mm][nn]);
                    wmma::mma_sync(acc[mm][nn], ah[mm], bl[nn], acc[mm][nn]);
                    wmma::mma_sync(acc[mm][nn], al[mm], bh[nn], acc[mm][nn]);
                }
        }
        __syncthreads();
    }

    #pragma unroll
    for (int mm = 0; mm < 2; ++mm)
        #pragma unroll
        for (int nn = 0; nn < 2; ++nn)
            wmma::store_matrix_sync(Cs + (warp_m*32 + mm*16)*68 + warp_n*32 + nn*16,
                                    acc[mm][nn], 68, wmma::mem_row_major);
    __syncthreads();

    // gate epilogue: 128 rows x 16 quads
    #pragma unroll
    for (int i = 0; i < 8; ++i) {
        int li = tid + (i << 8);
        int r = li >> 4, q = li & 15;
        long row = bm + r;
        if (row < NT) {
            int j = blockIdx.x*16 + q;
            const float* gs = Cs + r*68 + 4*q;
            const float* pp = L1 ? (pre + bn + 4*q) : (pre + row*(4*HD) + bn + 4*q);
            float ig = sigf(gs[0] + pp[0]);
            float fg = sigf(gs[1] + pp[1]);
            float gg = tanhf(gs[2] + pp[2]);
            float og = sigf(gs[3] + pp[3]);
            float c = first ? 0.f : cbuf[row*HD + j];
            c = fg*c + ig*gg;
            cbuf[row*HD + j] = c;
            hout[row*HD + j] = og*tanhf(c);
        }
    }
}

// ---------------- SIMT GEMM (dyn, fc) ----------------
#define BM 64
#define BN 64
#define BK 16
#define SPAD 4

template<int PRE, int ACT>
__global__ void gemm_k(const float* __restrict__ A,  const float* __restrict__ W1, int Ka,
                       const float* __restrict__ bias, const int* __restrict__ rowidx,
                       float* __restrict__ C, int M, int N)
{
    __shared__ float As[BK][BM+SPAD];
    __shared__ float Ws[BK][BN+SPAD];
    const int bm = blockIdx.y * BM, bn = blockIdx.x * BN;
    const int tid = threadIdx.x;
    const int tx = tid & 15, ty = tid >> 4;

    float acc[4][4] = {};

    const int ar = tid >> 2;
    const int ak = (tid & 3) << 2;
    const int wk = tid >> 4;
    const int wn = (tid & 15) << 2;

    const int arow_g = bm + ar;
    long arow = -1;
    if (arow_g < M) arow = rowidx ? (long)rowidx[arow_g] : (long)arow_g;

    for (int k0 = 0; k0 < Ka; k0 += BK) {
        float4 av = make_float4(0.f,0.f,0.f,0.f);
        if (arow >= 0) av = *(const float4*)(A + arow*(long)Ka + k0 + ak);
        if (PRE) { av.x=lk01(av.x); av.y=lk01(av.y); av.z=lk01(av.z); av.w=lk01(av.w); }
        As[ak  ][ar] = av.x;
        As[ak+1][ar] = av.y;
        As[ak+2][ar] = av.z;
        As[ak+3][ar] = av.w;
        float4 wv = *(const float4*)(W1 + (long)(k0+wk)*N + bn + wn);
        *(float4*)&Ws[wk][wn] = wv;
        __syncthreads();
        #pragma unroll
        for (int k = 0; k < BK; ++k) {
            float4 a4 = *(const float4*)&As[k][ty<<2];
            float4 b4 = *(const float4*)&Ws[k][tx<<2];
            acc[0][0]+=a4.x*b4.x; acc[0][1]+=a4.x*b4.y; acc[0][2]+=a4.x*b4.z; acc[0][3]+=a4.x*b4.w;
            acc[1][0]+=a4.y*b4.x; acc[1][1]+=a4.y*b4.y; acc[1][2]+=a4.y*b4.z; acc[1][3]+=a4.y*b4.w;
            acc[2][0]+=a4.z*b4.x; acc[2][1]+=a4.z*b4.y; acc[2][2]+=a4.z*b4.z; acc[2][3]+=a4.z*b4.w;
            acc[3][0]+=a4.w*b4.x; acc[3][1]+=a4.w*b4.y; acc[3][2]+=a4.w*b4.z; acc[3][3]+=a4.w*b4.w;
        }
        __syncthreads();
    }

    #pragma unroll
    for (int i = 0; i < 4; ++i) {
        int row = bm + (ty<<2) + i;
        if (row >= M) continue;
        #pragma unroll
        for (int j = 0; j < 4; ++j) {
            int col = bn + (tx<<2) + j;
            float v = acc[i][j];
            if (bias) v += bias[col];
            if (ACT == 1) v = lk01(v);
            C[(long)row*N + col] = v;
        }
    }
}

// ---------------- encoder embedding ----------------
__global__ void emb_kernel(const float* __restrict__ x, const float* __restrict__ ipW,
                           const float* __restrict__ ipb)
{
    long i = (long)blockIdx.x*blockDim.x + threadIdx.x;
    if (i >= (long)NN*TT*DE) return;
    long row = i >> 5; int j = (int)(i & 31);
    float v = x[row*2]*ipW[j] + x[row*2+1]*ipW[DE+j] + ipb[j];
    g_EMB[i] = lk01(v);
}

// ---------------- CSR build ----------------
__global__ void edge_count(const int* __restrict__ ei){
    int e = blockIdx.x*blockDim.x + threadIdx.x;
    if (e >= NE) return;
    int d = (e < NE0) ? ei[NE0+e] : (e - NE0);
    atomicAdd(&g_cnt[d], 1);
}
__global__ void scan_kernel(){
    __shared__ int sh[1024];
    __shared__ int run;
    int tid = threadIdx.x;
    if (tid == 0) run = 0;
    __syncthreads();
    for (int base = 0; base < NN; base += 1024) {
        int v = (base + tid < NN) ? g_cnt[base + tid] : 0;
        sh[tid] = v; __syncthreads();
        for (int off = 1; off < 1024; off <<= 1) {
            int tv = (tid >= off) ? sh[tid-off] : 0;
            __syncthreads();
            sh[tid] += tv;
            __syncthreads();
        }
        if (base + tid < NN) g_offs[base + tid + 1] = run + sh[tid];
        __syncthreads();
        if (tid == 0) run += sh[1023];
        __syncthreads();
    }
    if (tid == 0) g_offs[0] = 0;
}
__global__ void copy_cur(){
    int i = blockIdx.x*blockDim.x + threadIdx.x;
    if (i < NN) g_cur[i] = g_offs[i];
}
__global__ void edge_scatter(const int* __restrict__ ei){
    int e = blockIdx.x*blockDim.x + threadIdx.x;
    if (e >= NE) return;
    int s, d;
    if (e < NE0) { s = ei[e]; d = ei[NE0+e]; } else { s = e - NE0; d = s; }
    int pos = atomicAdd(&g_cur[d], 1);
    g_ssrc[pos] = s;
}

// ---------------- GAT ----------------
__global__ void attn_coef(const float* __restrict__ F, const float* __restrict__ a_s,
                          const float* __restrict__ a_d)
{
    int w = (blockIdx.x*blockDim.x + threadIdx.x) >> 5;
    if (w >= NN*3) return;
    int lane = threadIdx.x & 31;
    int node = w / 3, h = w - node*3;
    const float* f = F + (long)node*F3 + h*HE;
    const float* As_ = a_s + h*HE;
    const float* Ad_ = a_d + h*HE;
    float s1 = 0.f, s2 = 0.f;
    #pragma unroll
    for (int c = lane; c < HE; c += 32) { float fv = f[c]; s1 += fv*As_[c]; s2 += fv*Ad_[c]; }
    #pragma unroll
    for (int o = 16; o; o >>= 1) {
        s1 += __shfl_down_sync(0xffffffffu, s1, o);
        s2 += __shfl_down_sync(0xffffffffu, s2, o);
    }
    if (lane == 0) { g_asv[w] = s1; g_adv[w] = s2; }
}

__global__ void gat_agg(const float* __restrict__ F, const float* __restrict__ bias,
                        float* __restrict__ O)
{
    int w = (blockIdx.x*blockDim.x + threadIdx.x) >> 5;
    if (w >= NN) return;
    int lane = threadIdx.x & 31;
    int beg = g_offs[w], end = g_offs[w+1];
    float ad0 = g_adv[w*3], ad1 = g_adv[w*3+1], ad2 = g_adv[w*3+2];
    float m0 = -1e30f, m1 = -1e30f, m2 = -1e30f;
    float d0 = 0.f, d1 = 0.f, d2 = 0.f;
    float acc[12];
    #pragma unroll
    for (int q = 0; q < 12; ++q) acc[q] = 0.f;

    for (int p = beg; p < end; ++p) {
        int s = g_ssrc[p];
        float e0 = g_asv[s*3]   + ad0; e0 = (e0 >= 0.f) ? e0 : 0.2f*e0;
        float e1 = g_asv[s*3+1] + ad1; e1 = (e1 >= 0.f) ? e1 : 0.2f*e1;
        float e2 = g_asv[s*3+2] + ad2; e2 = (e2 >= 0.f) ? e2 : 0.2f*e2;
        const float* f = F + (long)s*F3;
        {
            float nm = fmaxf(m0, e0); float sc = __expf(m0-nm); float wv = __expf(e0-nm);
            d0 = d0*sc + wv;
            #pragma unroll
            for (int q = 0; q < 4; ++q) acc[q] = acc[q]*sc + wv*f[q*32 + lane];
            m0 = nm;
        }
        {
            float nm = fmaxf(m1, e1); float sc = __expf(m1-nm); float wv = __expf(e1-nm);
            d1 = d1*sc + wv;
            #pragma unroll
            for (int q = 0; q < 4; ++q) acc[4+q] = acc[4+q]*sc + wv*f[HE + q*32 + lane];
            m1 = nm;
        }
        {
            float nm = fmaxf(m2, e2); float sc = __expf(m2-nm); float wv = __expf(e2-nm);
            d2 = d2*sc + wv;
            #pragma unroll
            for (int q = 0; q < 4; ++q) acc[8+q] = acc[8+q]*sc + wv*f[2*HE + q*32 + lane];
            m2 = nm;
        }
    }
    float* o = O + (long)w*F3;
    #pragma unroll
    for (int q = 0; q < 4; ++q) {
        int c0 = q*32 + lane;
        o[c0]        = acc[q]  /d0 + bias[c0];
        o[HE + c0]   = acc[4+q]/d1 + bias[HE + c0];
        o[2*HE + c0] = acc[8+q]/d2 + bias[2*HE + c0];
    }
}

// ---------------- output head ----------------
__global__ void out_head(const float* __restrict__ h1, const float* __restrict__ opW,
                         const float* __restrict__ opb, float* __restrict__ out, int t)
{
    int w = (blockIdx.x*blockDim.x + threadIdx.x) >> 5;
    if (w >= NT) return;
    int lane = threadIdx.x & 31;
    const float* h = h1 + (long)w*HD;
    float s0 = 0.f, s1 = 0.f;
    #pragma unroll
    for (int k = lane; k < HD; k += 32) {
        float hv = h[k];
        s0 += hv*opW[k*2];
        s1 += hv*opW[k*2+1];
    }
    #pragma unroll
    for (int o = 16; o; o >>= 1) {
        s0 += __shfl_down_sync(0xffffffffu, s0, o);
        s1 += __shfl_down_sync(0xffffffffu, s1, o);
    }
    if (lane == 0) {
        long base = ((long)w*OUTL + t)*2;
        out[base]   = s0 + opb[0];
        out[base+1] = s1 + opb[1];
    }
}

// ---------------- host ----------------
static inline void mmagemm(const float* A, const __nv_bfloat16* Wh, const __nv_bfloat16* Wl, int K,
                           const float* bias, float* C, long M, int N)
{
    dim3 g(N/WBN, (unsigned)((M + WBM - 1)/WBM));
    mma_gemm<<<g, 256, MMA_SMEM>>>(A, Wh, Wl, K, bias, C, (int)M, N);
}

extern "C" void kernel_launch(void* const* d_in, const int* in_sizes, int n_in,
                              void* d_out, int out_size)
{
    const float* x    = (const float*)d_in[0];
    const int*   ei   = (const int*)  d_in[1];
    const int*   tgt  = (const int*)  d_in[2];
    const float* ipW  = (const float*)d_in[3];
    const float* ipb  = (const float*)d_in[4];
    const float* gWx  = (const float*)d_in[5];
    const float* gWh  = (const float*)d_in[6];
    const float* gbx  = (const float*)d_in[7];
    const float* gbh  = (const float*)d_in[8];
    const float* dynW = (const float*)d_in[9];
    const float* dynb = (const float*)d_in[10];
    const float* g1W  = (const float*)d_in[11];
    const float* g1as = (const float*)d_in[12];
    const float* g1ad = (const float*)d_in[13];
    const float* g1b  = (const float*)d_in[14];
    const float* g2W  = (const float*)d_in[15];
    const float* g2as = (const float*)d_in[16];
    const float* g2ad = (const float*)d_in[17];
    const float* g2b  = (const float*)d_in[18];
    const float* fcW  = (const float*)d_in[19];
    const float* fcb  = (const float*)d_in[20];
    const float* l0Wx = (const float*)d_in[21];
    const float* l0Wh = (const float*)d_in[22];
    const float* l0b  = (const float*)d_in[23];
    const float* l1Wx = (const float*)d_in[24];
    const float* l1Wh = (const float*)d_in[25];
    const float* l1b  = (const float*)d_in[26];
    const float* opW  = (const float*)d_in[27];
    const float* opb  = (const float*)d_in[28];
    float* out = (float*)d_out;
    (void)in_sizes; (void)n_in; (void)out_size;

    float *EMB,*GX,*H,*H2,*HENC,*F1,*O1,*F2,*O2,*ENC,*X0,*c0,*c1,*h0a,*h0b,*h1a,*h1b;
    float *gbxp,*gbhp,*l0bp,*l1bp;
    __nv_bfloat16 *WTh,*WTl;
    cudaGetSymbolAddress((void**)&EMB,  g_EMB);
    cudaGetSymbolAddress((void**)&GX,   g_GX);
    cudaGetSymbolAddress((void**)&H,    g_H);
    cudaGetSymbolAddress((void**)&H2,   g_H2);
    cudaGetSymbolAddress((void**)&HENC, g_HENC);
    cudaGetSymbolAddress((void**)&F1,   g_F1);
    cudaGetSymbolAddress((void**)&O1,   g_O1);
    cudaGetSymbolAddress((void**)&F2,   g_F2);
    cudaGetSymbolAddress((void**)&O2,   g_O2);
    cudaGetSymbolAddress((void**)&ENC,  g_ENC);
    cudaGetSymbolAddress((void**)&X0,   g_X0);
    cudaGetSymbolAddress((void**)&c0,   g_c0);
    cudaGetSymbolAddress((void**)&c1,   g_c1);
    cudaGetSymbolAddress((void**)&h0a,  g_h0a);
    cudaGetSymbolAddress((void**)&h0b,  g_h0b);
    cudaGetSymbolAddress((void**)&h1a,  g_h1a);
    cudaGetSymbolAddress((void**)&h1b,  g_h1b);
    cudaGetSymbolAddress((void**)&gbxp, g_gbxp);
    cudaGetSymbolAddress((void**)&gbhp, g_gbhp);
    cudaGetSymbolAddress((void**)&l0bp, g_l0bp);
    cudaGetSymbolAddress((void**)&l1bp, g_l1bp);
    cudaGetSymbolAddress((void**)&WTh,  g_WThi);
    cudaGetSymbolAddress((void**)&WTl,  g_WTlo);
    int *cntp;
    cudaGetSymbolAddress((void**)&cntp, g_cnt);

    static int attr_set = 0;
    if (!attr_set) {
        cudaFuncSetAttribute(gru_step, cudaFuncAttributeMaxDynamicSharedMemorySize, GRU_SMEM);
        attr_set = 1;
    }

    // weight offsets (elements)
    const int o_gWx  = 0;                      // [384'][32]  P=3
    const int o_gWh  = 12288;                  // [384'][128] P=3
    const int o_g1W  = 61440;                  // [384][128]
    const int o_g2W  = 110592;                 // [384][384]
    const int o_l0Wx = 258048;                 // [1024'][128] P=4
    const int o_l0Wh = 389120;                 // [1024'][256] P=4
    const int o_l1   = 651264;                 // [1024'][512] = [l1Wx|l1Wh] P=4

    // ---- weight prep ----
    wsplitp<<<(32*384+255)/256,256>>>(gWx,  WTh+o_gWx,  WTl+o_gWx,  32, 384, 3, 32, 0);
    wsplitp<<<(128*384+255)/256,256>>>(gWh,  WTh+o_gWh,  WTl+o_gWh,  128, 384, 3, 128, 0);
    wsplitp<<<(128*384+255)/256,256>>>(g1W,  WTh+o_g1W,  WTl+o_g1W,  128, 384, 1, 128, 0);
    wsplitp<<<(384*384+255)/256,256>>>(g2W,  WTh+o_g2W,  WTl+o_g2W,  384, 384, 1, 384, 0);
    wsplitp<<<(128*1024+255)/256,256>>>(l0Wx, WTh+o_l0Wx, WTl+o_l0Wx, 128, 1024, 4, 128, 0);
    wsplitp<<<(256*1024+255)/256,256>>>(l0Wh, WTh+o_l0Wh, WTl+o_l0Wh, 256, 1024, 4, 256, 0);
    wsplitp<<<(256*1024+255)/256,256>>>(l1Wx, WTh+o_l1,   WTl+o_l1,   256, 1024, 4, 512, 0);
    wsplitp<<<(256*1024+255)/256,256>>>(l1Wh, WTh+o_l1,   WTl+o_l1,   256, 1024, 4, 512, 256);
    bperm<<<2,256>>>(gbx, gbxp, 384, 3);
    bperm<<<2,256>>>(gbh, gbhp, 384, 3);
    bperm<<<4,256>>>(l0b, l0bp, 1024, 4);
    bperm<<<4,256>>>(l1b, l1bp, 1024, 4);

    // ---- CSR build ----
    zero_i<<<(NN+255)/256,256>>>(cntp, NN);
    edge_count<<<(NE+255)/256,256>>>(ei);
    scan_kernel<<<1,1024>>>();
    copy_cur<<<(NN+255)/256,256>>>();
    edge_scatter<<<(NE+255)/256,256>>>(ei);

    // ---- encoder ----
    emb_kernel<<<(int)(((long)NN*TT*DE + 255)/256),256>>>(x, ipW, ipb);
    mmagemm(EMB, WTh+o_gWx, WTl+o_gWx, 32, gbxp, GX, (long)NN*TT, F3);
    zero_f<<<(int)(((long)NN*HE + 255)/256),256>>>(H, (long)NN*HE);
    {
        dim3 gg(F3/96, (NN+127)/128);
        for (int t = 0; t < TT; ++t) {
            const float* hin  = (t & 1) ? H2 : H;
            float*       hout = (t & 1) ? H  : H2;
            gru_step<<<gg, 256, GRU_SMEM>>>(hin, WTh+o_gWh, WTl+o_gWh, hout, t);
        }
        // TT=16 even: final state in g_H
    }
    {
        dim3 g(HE/BN, (NN+BM-1)/BM);
        gemm_k<1,1><<<g,256>>>(H, dynW, HE, dynb, nullptr, HENC, NN, HE);
    }

    // ---- GAT layer 1 ----
    mmagemm(HENC, WTh+o_g1W, WTl+o_g1W, HE, nullptr, F1, NN, F3);
    attn_coef<<<(NN*3*32+255)/256,256>>>(F1, g1as, g1ad);
    gat_agg<<<(NN*32+255)/256,256>>>(F1, g1b, O1);

    // ---- GAT layer 2 ----
    mmagemm(O1, WTh+o_g2W, WTl+o_g2W, F3, nullptr, F2, NN, F3);
    attn_coef<<<(NN*3*32+255)/256,256>>>(F2, g2as, g2ad);
    gat_agg<<<(NN*32+255)/256,256>>>(F2, g2b, O2);

    // ---- target gather + fc ----
    {
        dim3 g(HE/BN, (NT+BM-1)/BM);
        gemm_k<0,1><<<g,256>>>(O2, fcW, F3, fcb, tgt, ENC, NT, HE);
    }

    // ---- decoder ----
    mmagemm(ENC, WTh+o_l0Wx, WTl+o_l0Wx, HE, l0bp, X0, NT, 4*HD);
    zero_f<<<((NT*HD)+255)/256,256>>>(h0a, (long)NT*HD);
    zero_f<<<((NT*HD)+255)/256,256>>>(h1a, (long)NT*HD);
    {
        dim3 gd(16, (NT+127)/128);
        for (int t = 0; t < OUTL; ++t) {
            float* h0in  = (t & 1) ? h0b : h0a;
            float* h0out = (t & 1) ? h0a : h0b;
            float* h1in  = (t & 1) ? h1b : h1a;
            float* h1out = (t & 1) ? h1a : h1b;
            dec_gemm<0><<<gd, 256, MMA_SMEM>>>(h0in, nullptr, WTh+o_l0Wh, WTl+o_l0Wh,
                                               X0, c0, h0out, t == 0);
            dec_gemm<1><<<gd, 256, MMA_SMEM>>>(h0out, h1in, WTh+o_l1, WTl+o_l1,
                                               l1bp, c1, h1out, t == 0);
            out_head<<<(NT*32+255)/256,256>>>(h1out, opW, opb, out, t);
        }
    }
}